// round 1
// baseline (speedup 1.0000x reference)
#include <cuda_runtime.h>

// ---------------------------------------------------------------------------
// MSELoss: out[0] = mean((yhat - y)^2) over 16384 x 4096 fp32.
// Two-pass deterministic reduction (no float atomics -> bitwise-stable).
// Pass 1: NBLK blocks, float4 grid-stride, block partial -> g_partials.
// Pass 2: one block reduces NBLK partials, divides by N.
// ---------------------------------------------------------------------------

#define NBLK 2048
#define NTHR 256

__device__ float g_partials[NBLK];

__global__ __launch_bounds__(NTHR) void mse_partial_kernel(
    const float* __restrict__ yhat,
    const float* __restrict__ y,
    long long n4)  // number of float4 elements
{
    const float4* __restrict__ a4 = reinterpret_cast<const float4*>(yhat);
    const float4* __restrict__ b4 = reinterpret_cast<const float4*>(y);

    float acc = 0.0f;
    long long stride = (long long)gridDim.x * blockDim.x;
    for (long long i = (long long)blockIdx.x * blockDim.x + threadIdx.x;
         i < n4; i += stride) {
        float4 a = a4[i];
        float4 b = b4[i];
        float d0 = a.x - b.x;
        float d1 = a.y - b.y;
        float d2 = a.z - b.z;
        float d3 = a.w - b.w;
        acc = fmaf(d0, d0, acc);
        acc = fmaf(d1, d1, acc);
        acc = fmaf(d2, d2, acc);
        acc = fmaf(d3, d3, acc);
    }

    // Warp reduction
    #pragma unroll
    for (int off = 16; off > 0; off >>= 1)
        acc += __shfl_xor_sync(0xFFFFFFFFu, acc, off);

    // Block reduction via smem
    __shared__ float warp_sums[NTHR / 32];
    int lane = threadIdx.x & 31;
    int wid  = threadIdx.x >> 5;
    if (lane == 0) warp_sums[wid] = acc;
    __syncthreads();

    if (wid == 0) {
        float v = (lane < NTHR / 32) ? warp_sums[lane] : 0.0f;
        #pragma unroll
        for (int off = 16; off > 0; off >>= 1)
            v += __shfl_xor_sync(0xFFFFFFFFu, v, off);
        if (lane == 0) g_partials[blockIdx.x] = v;
    }
}

__global__ __launch_bounds__(NTHR) void mse_final_kernel(
    float* __restrict__ out, float inv_n)
{
    // NBLK = 2048 partials, 256 threads -> 8 each
    float acc = 0.0f;
    #pragma unroll
    for (int i = 0; i < NBLK / NTHR; i++)
        acc += g_partials[threadIdx.x + i * NTHR];

    #pragma unroll
    for (int off = 16; off > 0; off >>= 1)
        acc += __shfl_xor_sync(0xFFFFFFFFu, acc, off);

    __shared__ float warp_sums[NTHR / 32];
    int lane = threadIdx.x & 31;
    int wid  = threadIdx.x >> 5;
    if (lane == 0) warp_sums[wid] = acc;
    __syncthreads();

    if (wid == 0) {
        float v = (lane < NTHR / 32) ? warp_sums[lane] : 0.0f;
        #pragma unroll
        for (int off = 16; off > 0; off >>= 1)
            v += __shfl_xor_sync(0xFFFFFFFFu, v, off);
        if (lane == 0) out[0] = v * inv_n;
    }
}

extern "C" void kernel_launch(void* const* d_in, const int* in_sizes, int n_in,
                              void* d_out, int out_size)
{
    const float* yhat = (const float*)d_in[0];
    const float* y    = (const float*)d_in[1];
    float* out        = (float*)d_out;

    long long n = (long long)in_sizes[0];   // 16384*4096 = 67108864, divisible by 4
    long long n4 = n / 4;

    mse_partial_kernel<<<NBLK, NTHR>>>(yhat, y, n4);
    mse_final_kernel<<<1, NTHR>>>(out, 1.0f / (float)n);
}